// round 6
// baseline (speedup 1.0000x reference)
#include <cuda_runtime.h>
#include <math.h>
#include <cstdint>

// Problem constants (fixed by reference: B=32, T=8192, K=16)
#define BT_ROWS   (32 * 8192)            // 262144 rows
#define KDIM      16
#define ELEMS     (BT_ROWS * KDIM)       // 4194304
#define NBLK      2048
#define NTHR      256
#define STRIDE    (NBLK * NTHR)          // 524288
#define ITER      (ELEMS / STRIDE)       // 8, exact
#define EPS_F     1e-7f
#define FULLMASK  0xffffffffu

// Per-block partial sums: [6][NBLK]
// j=0 fire_bce, j=1 live_count, j=2 valid_bce, j=3 cancel_ce, j=4 has_count, j=5 write_bce
__device__ float g_part[6 * NBLK];
__device__ unsigned int g_sem;   // zero-initialized; reset by last block each launch

__device__ __forceinline__ float warp_sum_f(float v) {
#pragma unroll
    for (int o = 16; o > 0; o >>= 1)
        v += __shfl_down_sync(FULLMASK, v, o);
    return v;
}
__device__ __forceinline__ double warp_sum_d(double v) {
#pragma unroll
    for (int o = 16; o > 0; o >>= 1)
        v += __shfl_down_sync(FULLMASK, v, o);
    return v;
}

struct Elem {
    int   c, o, ct;
    float th, vv, tf, tv;
    int   lm;
};

__global__ __launch_bounds__(NTHR, 5)
void lifecycle_fused(const float* __restrict__ trig,          // (B,T,K)
                     const float* __restrict__ vld,           // (B,T,K)
                     const float* __restrict__ clog,          // (B,T,K,3)
                     const float* __restrict__ wsc,           // (B,T,1)
                     const void*  __restrict__ live_raw,      // (B,T,K) bool, dtype sniffed
                     const int*   __restrict__ cid,           // (B,T,K)
                     const float* __restrict__ ofire,         // (B,T,K)
                     const int*   __restrict__ ocan,          // (B,T,K)
                     const float* __restrict__ ovld,          // (B,T,K)
                     const float* __restrict__ osw,           // (B,T,1)
                     const int*   __restrict__ ocid,          // (B,T,K)
                     float* __restrict__ out)                 // (5,)
{
    // ---- Inline live_mask dtype sniff (all blocks read same 64 words; L2 broadcast) ----
    // mode 0 = uint8 bytes, 1 = int32 words, 2 = float32 words
    __shared__ unsigned int s_or, s_f32;
    __shared__ int s_mode;
    if (threadIdx.x == 0) { s_or = 0u; s_f32 = 0u; }
    __syncthreads();
    if (threadIdx.x < 64) {
        unsigned int x = ((const unsigned int*)live_raw)[threadIdx.x];
        unsigned int f = (x == 0x3F800000u) ? 1u : 0u;
        unsigned int a = f ? 0u : x;
#pragma unroll
        for (int o = 16; o > 0; o >>= 1) {
            a |= __shfl_down_sync(FULLMASK, a, o);
            f |= __shfl_down_sync(FULLMASK, f, o);
        }
        if ((threadIdx.x & 31) == 0) { atomicOr(&s_or, a); atomicOr(&s_f32, f); }
    }
    __syncthreads();
    if (threadIdx.x == 0)
        s_mode = s_f32 ? 2 : ((s_or & ~1u) ? 0 : 1);
    __syncthreads();
    const int mode = s_mode;

    const unsigned int lane  = threadIdx.x & 31;
    const unsigned int gbase = lane & ~15u;   // 16-lane row group base within warp
    const int e0 = blockIdx.x * NTHR + threadIdx.x;

    float fire_s = 0.f, m_s = 0.f, val_s = 0.f, can_s = 0.f, has_s = 0.f, w_s = 0.f;

    // ---- load stage (8 independent LDGs) ----
    auto load_elem = [&](int e) -> Elem {
        Elem r;
        r.c  = cid[e];
        r.o  = ocid[e];
        r.th = trig[e];
        r.vv = vld[e];
        r.tf = ofire[e];
        r.tv = ovld[e];
        r.ct = ocan[e];
        if (mode == 0)      r.lm = ((const unsigned char*)live_raw)[e] != 0;
        else if (mode == 1) r.lm = ((const int*)live_raw)[e] != 0;
        else                r.lm = ((const float*)live_raw)[e] != 0.0f;
        return r;
    };

    // ---- 2-stage software pipeline over ITER iterations ----
    Elem cur = load_elem(e0);
#pragma unroll
    for (int it = 0; it < ITER; ++it) {
        Elem nxt;
        if (it + 1 < ITER) nxt = load_elem(e0 + (it + 1) * STRIDE);

        const int e = e0 + it * STRIDE;

        // First-match scan across the 16-lane row group via shuffles
        int idx = 16;
#pragma unroll
        for (int ko = 15; ko >= 0; --ko) {
            int ov = __shfl_sync(FULLMASK, cur.o, gbase + ko, 32);
            if (ov == cur.c) idx = ko;
        }
        const bool fnd = (idx < 16) && (cur.c != 0);
        const int  src = gbase + (fnd ? idx : 0);

        // Gather oracle targets via shuffle (lanes already hold them)
        float tf = __shfl_sync(FULLMASK, cur.tf, src, 32);
        float tv = __shfl_sync(FULLMASK, cur.tv, src, 32);
        int   ct = __shfl_sync(FULLMASK, cur.ct, src, 32);
        if (!fnd) { tf = 0.f; tv = 0.f; ct = 0; }

        if (cur.lm) {
            m_s += 1.0f;

            float p = fminf(fmaxf(cur.th, EPS_F), 1.0f - EPS_F);
            fire_s -= tf * __logf(p) + (1.0f - tf) * __logf(1.0f - p);

            float q = fminf(fmaxf(cur.vv, EPS_F), 1.0f - EPS_F);
            val_s -= tv * __logf(q) + (1.0f - tv) * __logf(1.0f - q);

            if (ct > 0) {
                const float* lp = clog + (size_t)e * 3;
                float x0 = lp[0], x1 = lp[1], x2 = lp[2];
                float mx = fmaxf(x0, fmaxf(x1, x2));
                float s  = __expf(x0 - mx) + __expf(x1 - mx) + __expf(x2 - mx);
                int tgt = ct - 1;
                tgt = tgt < 0 ? 0 : (tgt > 2 ? 2 : tgt);
                float xt = (tgt == 0) ? x0 : ((tgt == 1) ? x1 : x2);
                can_s += mx + __logf(s) - xt;
                has_s += 1.0f;
            }
        }

        // write-head BCE-with-logits: one per row (lane with k==0)
        if ((e & 15) == 0) {
            const int row = e >> 4;
            float wx = wsc[row], wy = osw[row];
            w_s += fmaxf(wx, 0.0f) - wx * wy + __logf(1.0f + __expf(-fabsf(wx)));
        }

        cur = nxt;
    }

    // ---- Deterministic block reduction of 6 float accumulators ----
    __shared__ float sm[8][6];
    {
        float vals[6] = {fire_s, m_s, val_s, can_s, has_s, w_s};
#pragma unroll
        for (int j = 0; j < 6; ++j) vals[j] = warp_sum_f(vals[j]);
        const int wid = threadIdx.x >> 5, lid = threadIdx.x & 31;
        if (lid == 0) {
#pragma unroll
            for (int j = 0; j < 6; ++j) sm[wid][j] = vals[j];
        }
        __syncthreads();
        if (wid == 0) {
#pragma unroll
            for (int j = 0; j < 6; ++j) {
                float v = (lid < (NTHR / 32)) ? sm[lid][j] : 0.0f;
                v = warp_sum_f(v);
                if (lid == 0) g_part[j * NBLK + blockIdx.x] = v;
            }
        }
    }

    // ---- Last-block finalize (threadfence reduction) ----
    __shared__ int s_last;
    if (threadIdx.x == 0) {
        __threadfence();
        unsigned int t = atomicAdd(&g_sem, 1u);
        s_last = (t == NBLK - 1) ? 1 : 0;
    }
    __syncthreads();
    if (!s_last) return;

    __shared__ double smd[8];
    double tot[6];
#pragma unroll
    for (int j = 0; j < 6; ++j) {
        double v = 0.0;
        for (int i = threadIdx.x; i < NBLK; i += NTHR)
            v += (double)__ldcg(&g_part[j * NBLK + i]);
        v = warp_sum_d(v);
        const int wid = threadIdx.x >> 5, lid = threadIdx.x & 31;
        if (lid == 0) smd[wid] = v;
        __syncthreads();
        double r = 0.0;
        if (wid == 0) {
            r = (lid < (NTHR / 32)) ? smd[lid] : 0.0;
            r = warp_sum_d(r);
        }
        tot[j] = r;  // valid on thread 0
        __syncthreads();
    }
    if (threadIdx.x == 0) {
        double n     = fmax(tot[1], 1.0);
        double fire  = tot[0] / n;                                        // LAM_FIRE   = 1.0
        double canc  = (tot[4] > 0.0) ? tot[3] / fmax(tot[4], 1.0) : 0.0; // LAM_CANCEL = 1.0
        double valid = 0.5 * tot[2] / n;                                  // LAM_VALID  = 0.5
        double wr    = 0.5 * tot[5] / (double)BT_ROWS;                    // LAM_WRITE  = 0.5
        out[0] = (float)fire;
        out[1] = (float)canc;
        out[2] = (float)valid;
        out[3] = (float)wr;
        out[4] = (float)(fire + canc + valid + wr);
        g_sem = 0;   // reset for next graph replay
    }
}

extern "C" void kernel_launch(void* const* d_in, const int* in_sizes, int n_in,
                              void* d_out, int out_size)
{
    (void)in_sizes; (void)n_in; (void)out_size;
    lifecycle_fused<<<NBLK, NTHR>>>(
        (const float*)d_in[0],          // trigger_hazard
        (const float*)d_in[1],          // validity
        (const float*)d_in[2],          // cancel_logits
        (const float*)d_in[3],          // write_score
        d_in[4],                        // live_mask (dtype auto-detected)
        (const int*)d_in[5],            // contract_id
        (const float*)d_in[6],          // oracle_fire
        (const int*)d_in[7],            // oracle_cancel
        (const float*)d_in[8],          // oracle_valid
        (const float*)d_in[9],          // oracle_should_write
        (const int*)d_in[10],           // oracle_contract_id
        (float*)d_out);
}